// round 1
// baseline (speedup 1.0000x reference)
#include <cuda_runtime.h>
#include <cstdint>

// Problem constants
#define BDIM 8
#define TDIM 8192
#define KDIM 64
#define DDIM 128
#define NCHK 64          // chunks per batch along T
#define LCHK 128         // chunk length  = TDIM/NCHK
#define TG   8           // t-groups per block
#define LSUB 16          // elements per thread = LCHK/TG

// ---------------- scratch (device globals; no allocation) ----------------
__device__ float  g_u[BDIM * TDIM * KDIM];          // raw x @ W^T (16.8 MB)
__device__ float4 g_agg [BDIM * NCHK * KDIM];       // chunk aggregates (A,B complex)
__device__ float4 g_pref[BDIM * NCHK * KDIM];       // inclusive prefixes
__device__ int    g_flag[BDIM * NCHK];              // 0=none 1=agg 2=prefix
__device__ float  g_inv_sigma;

// ---------------- acquire/release helpers ----------------
__device__ __forceinline__ int ld_acquire(const int* p) {
    int v;
    asm volatile("ld.acquire.gpu.s32 %0, [%1];" : "=r"(v) : "l"(p) : "memory");
    return v;
}
__device__ __forceinline__ void st_release(int* p, int v) {
    asm volatile("st.release.gpu.s32 [%0], %1;" :: "l"(p), "r"(v) : "memory");
}

// =========================================================================
// Kernel 1: GEMM (u_raw = x @ W^T) + sigma(W) power iteration + flag clear
// Grid: 256 GEMM blocks + 1 sigma block, 256 threads each.
// =========================================================================
__global__ __launch_bounds__(256) void gemm_sigma_kernel(
    const float* __restrict__ x, const float* __restrict__ W)
{
    __shared__ float pool[8192 + 2304];   // GEMM: ws[64*128] + xs[256*9] ; sigma aliases
    const int tid = threadIdx.x;

    if (blockIdx.x < 256) {
        // ---------------- GEMM path: 256 rows per block, 1 row/thread ------
        float* ws = pool;           // W, [64][128] row-major (k-major)
        float* xs = pool + 8192;    // [256][9]  (8 d-values + 1 pad)

        for (int i = tid; i < 2048; i += 256)
            ((float4*)ws)[i] = ((const float4*)W)[i];

        float acc[64];
        #pragma unroll
        for (int c = 0; c < 64; c++) acc[c] = 0.f;

        const int row0 = blockIdx.x * 256;
        const float* xb = x + (size_t)row0 * DDIM;

        for (int ch = 0; ch < 16; ch++) {          // 16 chunks of 8 d's
            __syncthreads();
            // stage x[256 rows][8 d] : each thread loads its own row's 8 floats
            {
                float4 v0 = *(const float4*)(xb + (size_t)tid * DDIM + ch * 8);
                float4 v1 = *(const float4*)(xb + (size_t)tid * DDIM + ch * 8 + 4);
                float* d = &xs[tid * 9];
                d[0]=v0.x; d[1]=v0.y; d[2]=v0.z; d[3]=v0.w;
                d[4]=v1.x; d[5]=v1.y; d[6]=v1.z; d[7]=v1.w;
            }
            __syncthreads();
            #pragma unroll
            for (int dq = 0; dq < 2; dq++) {
                float x0 = xs[tid*9 + dq*4 + 0];
                float x1 = xs[tid*9 + dq*4 + 1];
                float x2 = xs[tid*9 + dq*4 + 2];
                float x3 = xs[tid*9 + dq*4 + 3];
                #pragma unroll
                for (int c = 0; c < 64; c++) {
                    float4 wv = *(const float4*)&ws[c*DDIM + ch*8 + dq*4]; // broadcast
                    acc[c] += x0*wv.x + x1*wv.y + x2*wv.z + x3*wv.w;
                }
            }
        }
        float4* up = (float4*)&g_u[(size_t)(row0 + tid) * KDIM];
        #pragma unroll
        for (int c = 0; c < 16; c++)
            up[c] = make_float4(acc[4*c], acc[4*c+1], acc[4*c+2], acc[4*c+3]);
    } else {
        // ---------------- sigma block: clear flags + power iteration -------
        for (int i = tid; i < BDIM * NCHK; i += 256) g_flag[i] = 0;

        float* Ms = pool;            // [64][65]
        float* v0 = pool + 4224;     // 64
        float* v1 = pool + 4288;     // 64

        // M = W W^T  (reads W straight from global; L1-resident)
        for (int e = tid; e < 4096; e += 256) {
            int r = e >> 6, cc = e & 63;
            const float4* a = (const float4*)(W + r  * DDIM);
            const float4* b = (const float4*)(W + cc * DDIM);
            float s = 0.f;
            #pragma unroll
            for (int d = 0; d < 32; d++) {
                float4 av = a[d], bv = b[d];
                s += av.x*bv.x + av.y*bv.y + av.z*bv.z + av.w*bv.w;
            }
            Ms[r*65 + cc] = s;
        }
        if (tid < 64) v0[tid] = 1.0f;
        __syncthreads();

        const int r = tid >> 2, part = tid & 3;   // 4 threads per row
        float* va = v0; float* vb = v1;
        for (int it = 0; it < 256; it++) {
            float s = 0.f;
            #pragma unroll
            for (int j = 0; j < 16; j++)
                s += Ms[r*65 + part*16 + j] * va[part*16 + j];
            s += __shfl_xor_sync(0xffffffffu, s, 1);
            s += __shfl_xor_sync(0xffffffffu, s, 2);
            if (part == 0) vb[r] = ((it & 31) == 31) ? s * 1e-14f : s;
            __syncthreads();
            float* t = va; va = vb; vb = t;
        }
        // Rayleigh quotient: lambda = (v . Mv)/(v . v)
        {
            float s = 0.f;
            #pragma unroll
            for (int j = 0; j < 16; j++)
                s += Ms[r*65 + part*16 + j] * va[part*16 + j];
            s += __shfl_xor_sync(0xffffffffu, s, 1);
            s += __shfl_xor_sync(0xffffffffu, s, 2);
            if (part == 0) vb[r] = s;
        }
        __syncthreads();
        if (tid == 0) {
            float num = 0.f, den = 0.f;
            for (int j = 0; j < 64; j++) { num += va[j]*vb[j]; den += va[j]*va[j]; }
            g_inv_sigma = 1.0f / sqrtf(num / den);   // 1/sigma_max(W)
        }
    }
}

// =========================================================================
// Kernel 2: fused elementwise + single-pass scan with decoupled look-back.
// Grid: BDIM*NCHK blocks (blk = b*NCHK + c), 512 threads = 64 k x 8 tgroups.
// =========================================================================
__global__ __launch_bounds__(512, 1) void scan_kernel(
    const float* __restrict__ dt,   const float* __restrict__ amod,
    const float* __restrict__ omod, const float* __restrict__ tmod,
    const float* __restrict__ srr,  const float* __restrict__ sim,
    const float* __restrict__ traw, const float* __restrict__ bias,
    float* __restrict__ out)
{
    __shared__ float sAr[TG][KDIM], sAi[TG][KDIM], sBr[TG][KDIM], sBi[TG][KDIM];
    __shared__ float4 sE[KDIM];

    const int tid = threadIdx.x;
    const int k   = tid & 63;
    const int tg  = tid >> 6;
    const int blk = blockIdx.x;
    const int bb  = blk >> 6;        // batch
    const int c   = blk & 63;        // chunk
    const int tbase = c * LCHK + tg * LSUB;
    const size_t bt0 = (size_t)bb * TDIM;

    // per-k constants
    float tr  = traw[0];
    float tau = ((tr > 20.f) ? tr : log1pf(expf(tr))) + 1e-3f;
    float sr  = srr[k];
    float sp  = (sr > 20.f) ? sr : log1pf(expf(sr));
    float alpha0 = (sp + 1e-6f) * tau;
    float omega0 = sim[k] * tau;
    float bk     = bias[k];
    float invsig = g_inv_sigma;

    // -------- phase 1: per-thread local sweep, keep (a,u) in registers ----
    float ar[LSUB], ai[LSUB], uu[LSUB];
    float Ar = 1.f, Ai = 0.f, Br = 0.f, Bi = 0.f;
    #pragma unroll
    for (int i = 0; i < LSUB; i++) {
        const size_t bt  = bt0 + (tbase + i);
        const size_t idx = bt * KDIM + k;
        float amv = amod[idx], omv = omod[idx];
        float scale = __expf(tmod[bt]);
        float dtv   = dt[bt];
        float alpha = alpha0 * __expf(amv) * scale;
        float omega = omega0 * __expf(omv) * scale;
        float rho   = __expf(-alpha * dtv);
        float th    = omega * dtv;
        float sn, cs; __sincosf(th, &sn, &cs);
        float car = rho * cs, cai = rho * sn;
        float uv  = g_u[idx] * invsig + bk;
        ar[i] = car; ai[i] = cai; uu[i] = uv;
        float nbr = car*Br - cai*Bi + uv;
        float nbi = car*Bi + cai*Br;
        Br = nbr; Bi = nbi;
        float nar = car*Ar - cai*Ai;
        float nai = car*Ai + cai*Ar;
        Ar = nar; Ai = nai;
    }
    sAr[tg][k] = Ar; sAi[tg][k] = Ai; sBr[tg][k] = Br; sBi[tg][k] = Bi;
    __syncthreads();

    // -------- phase 2: block scan of tgroup aggregates (threads 0..63) ----
    float bAr = 1.f, bAi = 0.f, bBr = 0.f, bBi = 0.f;
    if (tid < 64) {
        float rAr = 1.f, rAi = 0.f, rBr = 0.f, rBi = 0.f;
        #pragma unroll
        for (int g = 0; g < TG; g++) {
            float aAr = sAr[g][k], aAi = sAi[g][k];
            float aBr = sBr[g][k], aBi = sBi[g][k];
            sAr[g][k] = rAr; sAi[g][k] = rAi;           // exclusive-in-block
            sBr[g][k] = rBr; sBi[g][k] = rBi;
            float nAr = aAr*rAr - aAi*rAi;
            float nAi = aAr*rAi + aAi*rAr;
            float nBr = aAr*rBr - aAi*rBi + aBr;
            float nBi = aAr*rBi + aAi*rBr + aBi;
            rAr = nAr; rAi = nAi; rBr = nBr; rBi = nBi;
        }
        bAr = rAr; bAi = rAi; bBr = rBr; bBi = rBi;
        g_agg[(blk << 6) | k] = make_float4(bAr, bAi, bBr, bBi);
        if (c == 0) g_pref[(blk << 6) | k] = make_float4(bAr, bAi, bBr, bBi);
    }
    __syncthreads();
    if (tid == 0) st_release(&g_flag[blk], (c == 0) ? 2 : 1);

    // -------- look-back (warps 0-1 only; per-k values, shared flag) -------
    if (tid < 64) {
        if (c > 0) {
            float RAr = 1.f, RAi = 0.f, RBr = 0.f, RBi = 0.f;
            float EAr, EAi, EBr, EBi;
            int j = c - 1;
            while (true) {
                int f = ld_acquire(&g_flag[(bb << 6) | j]);
                if (f == 0) { __nanosleep(40); continue; }
                if (f == 2) {
                    float4 vv = g_pref[((size_t)((bb << 6) | j) << 6) | k];
                    EAr = RAr*vv.x - RAi*vv.y;
                    EAi = RAr*vv.y + RAi*vv.x;
                    EBr = RAr*vv.z - RAi*vv.w + RBr;
                    EBi = RAr*vv.w + RAi*vv.z + RBi;
                    break;
                } else {
                    float4 vv = g_agg[((size_t)((bb << 6) | j) << 6) | k];
                    float nAr = RAr*vv.x - RAi*vv.y;
                    float nAi = RAr*vv.y + RAi*vv.x;
                    float nBr = RAr*vv.z - RAi*vv.w + RBr;
                    float nBi = RAr*vv.w + RAi*vv.z + RBi;
                    RAr = nAr; RAi = nAi; RBr = nBr; RBi = nBi;
                    if (--j < 0) { EAr=RAr; EAi=RAi; EBr=RBr; EBi=RBi; break; }
                }
            }
            // inclusive prefix = blockAgg ∘ E
            float PAr = bAr*EAr - bAi*EAi;
            float PAi = bAr*EAi + bAi*EAr;
            float PBr = bAr*EBr - bAi*EBi + bBr;
            float PBi = bAr*EBi + bAi*EBr + bBi;
            g_pref[(blk << 6) | k] = make_float4(PAr, PAi, PBr, PBi);
            sE[k] = make_float4(EAr, EAi, EBr, EBi);
        } else {
            sE[k] = make_float4(1.f, 0.f, 0.f, 0.f);
        }
    }
    __syncthreads();
    if (tid == 0 && c > 0) st_release(&g_flag[blk], 2);

    // -------- phase 3: reapply with true carry, write output --------------
    float4 E = sE[k];
    float tAr = sAr[tg][k], tAi = sAi[tg][k];
    float tBr = sBr[tg][k], tBi = sBi[tg][k];
    float hr = tAr*E.z - tAi*E.w + tBr;   // h at segment start (init state = 0)
    float hi = tAr*E.w + tAi*E.z + tBi;
    #pragma unroll
    for (int i = 0; i < LSUB; i++) {
        float nr = ar[i]*hr - ai[i]*hi + uu[i];
        float ni = ar[i]*hi + ai[i]*hr;
        hr = nr; hi = ni;
        const size_t ob = (bt0 + (tbase + i)) * (size_t)(2 * KDIM);
        out[ob + k]        = hr;   // C
        out[ob + KDIM + k] = hi;   // S
    }
}

// =========================================================================
extern "C" void kernel_launch(void* const* d_in, const int* in_sizes, int n_in,
                              void* d_out, int out_size)
{
    (void)in_sizes; (void)n_in; (void)out_size;
    const float* x    = (const float*)d_in[0];
    const float* dt   = (const float*)d_in[1];
    const float* amod = (const float*)d_in[2];
    const float* omod = (const float*)d_in[3];
    const float* tmod = (const float*)d_in[4];
    const float* srr  = (const float*)d_in[5];
    const float* sim  = (const float*)d_in[6];
    const float* traw = (const float*)d_in[7];
    const float* W    = (const float*)d_in[8];
    const float* bias = (const float*)d_in[9];
    float* out = (float*)d_out;

    gemm_sigma_kernel<<<257, 256>>>(x, W);
    scan_kernel<<<BDIM * NCHK, 512>>>(dt, amod, omod, tmod, srr, sim, traw, bias, out);
}